// round 2
// baseline (speedup 1.0000x reference)
#include <cuda_runtime.h>

// Problem constants
#define Bz   2
#define Cc   3
#define Hh   160
#define Ww   160
#define SPAN 11
#define KK   23              // 2*SPAN+1
#define PH   (Hh + 2*SPAN)   // 182
#define PW   (Ww + 2*SPAN)   // 182
#define NPIX (Bz*Hh*Ww)      // 51200
#define HW   (Hh*Ww)

// Scratch (__device__ globals: zero-initialized at module load; pad regions of
// g_simg/g_yhat are never written, so they stay zero across graph replays).
__device__ float4 g_simg[Bz*PH*PW];   // {10*r, 10*g, 10*b, src}; pad = 0
__device__ float4 g_yhat[Bz*PH*PW];   // {src*y0, src*y1, src*y2, 0}; pad = 0
__device__ float4 g_cw[NPIX];         // center weights {1-y0, 1-y1, 1-y2, 0}
__device__ int    g_list[NPIX];       // compacted active-pixel indices
__device__ int    g_count;
__device__ double g_ce;
__device__ double g_gcrf;

__device__ __forceinline__ float ex2f(float x) {
    float y;
    asm("ex2.approx.f32 %0, %1;" : "=f"(y) : "f"(x));
    return y;
}

__global__ void init_kernel() {
    if (threadIdx.x == 0) { g_count = 0; g_ce = 0.0; g_gcrf = 0.0; }
}

// One thread per pixel: softmax, CE term, staging of padded float4 arrays,
// warp-aggregated compaction of active pixels (destination_map == 0).
__global__ void __launch_bounds__(256) prep_kernel(
    const float* __restrict__ logit, const int* __restrict__ target,
    const float* __restrict__ image, const float* __restrict__ srcmap,
    const float* __restrict__ dstmap)
{
    int t = blockIdx.x * blockDim.x + threadIdx.x;   // t in [0, NPIX)
    float ce = 0.f;
    bool active = false;

    if (t < NPIX) {
        int b  = t / HW;
        int hw = t - b * HW;
        int i  = hw / Ww;
        int j  = hw - i * Ww;

        const float* lg = logit + (size_t)b * Cc * HW + hw;
        float l0 = lg[0], l1 = lg[HW], l2 = lg[2*HW];
        float m  = fmaxf(l0, fmaxf(l1, l2));
        float e0 = expf(l0 - m), e1 = expf(l1 - m), e2 = expf(l2 - m);
        float s  = e0 + e1 + e2;
        float inv = 1.f / s;
        float y0 = e0*inv, y1 = e1*inv, y2 = e2*inv;

        int   tg  = target[t];
        float lt  = (tg == 0) ? l0 : ((tg == 1) ? l1 : l2);
        float dst = dstmap[t];
        ce = -((lt - m) - logf(s)) * dst;

        const float* im = image + (size_t)b * 3 * HW + hw;
        float src = srcmap[t];
        int pidx = (b * PH + i + SPAN) * PW + (j + SPAN);
        g_simg[pidx] = make_float4(10.f*im[0], 10.f*im[HW], 10.f*im[2*HW], src);
        g_yhat[pidx] = make_float4(src*y0, src*y1, src*y2, 0.f);
        g_cw[t]      = make_float4(1.f - y0, 1.f - y1, 1.f - y2, 0.f);

        active = (dst == 0.0f);   // m_dst = 1 - dst
    }

    // Warp-aggregated compaction (keeps within-warp pixel contiguity)
    unsigned mask = __ballot_sync(0xffffffffu, active);
    if (mask) {
        int lane   = threadIdx.x & 31;
        int leader = __ffs(mask) - 1;
        int base   = 0;
        if (lane == leader) base = atomicAdd(&g_count, __popc(mask));
        base = __shfl_sync(0xffffffffu, base, leader);
        if (active) {
            int off = __popc(mask & ((1u << lane) - 1));
            g_list[base + off] = t;
        }
    }

    // Block reduce CE -> one double atomic per block
    __shared__ float red[256];
    red[threadIdx.x] = ce;
    __syncthreads();
    for (int s2 = 128; s2 > 0; s2 >>= 1) {
        if (threadIdx.x < s2) red[threadIdx.x] += red[threadIdx.x + s2];
        __syncthreads();
    }
    if (threadIdx.x == 0) atomicAdd(&g_ce, (double)red[0]);
}

// Main window kernel: one thread per ACTIVE pixel, 529-offset branch-free loop.
__global__ void __launch_bounds__(256) main_kernel()
{
    const float C1 = -0.72134752f;          // -0.5 * log2(e)
    int idx = blockIdx.x * blockDim.x + threadIdx.x;
    int n   = g_count;
    float acc = 0.f;

    if (idx < n) {
        int t  = g_list[idx];
        int b  = t / HW;
        int hw = t - b * HW;
        int i  = hw / Ww;
        int j  = hw - i * Ww;
        int base = (b * PH + i) * PW + j;   // window corner in padded coords

        float4 ci = g_simg[base + SPAN*PW + SPAN];
        float c0 = 0.1f*ci.x, c1 = 0.1f*ci.y, c2 = 0.1f*ci.z;   // unscaled center
        float4 cw = g_cw[t];
        float w0 = cw.x, w1 = cw.y, w2 = cw.z;

        // spatial factor along j, per thread in registers (dj fully unrolled)
        float fj[KK];
        #pragma unroll
        for (int d = 0; d < KK; d++) {
            float xj = (float)(5*j - d + SPAN) * (1.f/6.f);
            fj[d] = ex2f(xj*xj*C1);
        }

        #pragma unroll 1
        for (int di = 0; di < KK; di++) {
            float xi = (float)(5*i - di + SPAN) * (1.f/6.f);
            float fi = ex2f(xi*xi*C1);
            const float4* pim = g_simg + base + di*PW;
            const float4* pyh = g_yhat + base + di*PW;
            #pragma unroll
            for (int dj = 0; dj < KK; dj++) {
                float4 nb = __ldg(pim + dj);   // {10r,10g,10b, src}
                float4 ny = __ldg(pyh + dj);   // src-gated yhat (0 OOB)
                float d0 = c0 - nb.x, d1 = c1 - nb.y, d2 = c2 - nb.z;
                float ss = fmaf(d2, d2, fmaf(d1, d1, d0*d0));
                float krgb = ex2f(ss * C1);              // exp(-0.5*ss)
                float km   = fmaf(fi, fj[dj], krgb);     // k_rgb + k_xy
                float sn   = fmaf(ny.z, w2, fmaf(ny.y, w1, ny.x*w0));
                acc = fmaf(km, sn, acc);                 // gate folded into ny
            }
        }
    }

    __shared__ float red[256];
    red[threadIdx.x] = acc;
    __syncthreads();
    for (int s2 = 128; s2 > 0; s2 >>= 1) {
        if (threadIdx.x < s2) red[threadIdx.x] += red[threadIdx.x + s2];
        __syncthreads();
    }
    if (threadIdx.x == 0) atomicAdd(&g_gcrf, (double)red[0]);
}

__global__ void fin_kernel(float* out) {
    out[0] = (float)((g_ce + 0.15 * g_gcrf) / (double)NPIX);
}

extern "C" void kernel_launch(void* const* d_in, const int* in_sizes, int n_in,
                              void* d_out, int out_size)
{
    const float* logit  = (const float*)d_in[0];
    const int*   target = (const int*)  d_in[1];
    const float* image  = (const float*)d_in[2];
    const float* srcmap = (const float*)d_in[3];
    const float* dstmap = (const float*)d_in[4];
    float* out = (float*)d_out;

    init_kernel<<<1, 32>>>();
    prep_kernel<<<NPIX/256, 256>>>(logit, target, image, srcmap, dstmap);
    main_kernel<<<NPIX/256, 256>>>();   // inactive tail guarded via g_count
    fin_kernel<<<1, 1>>>(out);
}

// round 3
// speedup vs baseline: 1.1191x; 1.1191x over previous
#include <cuda_runtime.h>

// Problem constants
#define Bz   2
#define Hh   160
#define Ww   160
#define SPAN 11
#define KK   23              // 2*SPAN+1
#define PH   (Hh + 2*SPAN)   // 182
#define PW   (Ww + 2*SPAN)   // 182
#define NPIX (Bz*Hh*Ww)      // 51200
#define HW   (Hh*Ww)

#define NBLK 148             // one persistent block per SM
#define NTHR 512

// s = sqrt(0.5*log2(e)); image staged pre-scaled by 10*s so exp arg is -sum(d'^2)
#define SSC  0.8493218f
#define C1   (-0.72134752f)  // -0.5*log2(e), for spatial kernel

// __device__ globals: zero-initialized at load; pad regions never written;
// all mutable state self-resets at the end of each launch (graph-replay safe).
__device__ float4   g_simg[Bz*PH*PW];  // {10s*r, 10s*g, 10s*b, src}; pad = 0
__device__ float4   g_yhat[Bz*PH*PW];  // {src*y0, src*y1, src*y2, 0}; pad = 0
__device__ float4   g_cw[NPIX];        // center softmax {y0,y1,y2,0}
__device__ int      g_list[NPIX];      // compacted active-pixel indices
__device__ int      g_count;
__device__ unsigned g_bar1;            // grid barrier (prep -> window)
__device__ unsigned g_unit;            // dynamic work counter (window phase)
__device__ unsigned g_done;            // completion ticket (fin phase)
__device__ double   g_ce;
__device__ double   g_gcrf;

__device__ __forceinline__ float ex2f(float x) {
    float y;
    asm("ex2.approx.f32 %0, %1;" : "=f"(y) : "f"(x));
    return y;
}

__global__ void __launch_bounds__(NTHR, 1) fused_kernel(
    const float* __restrict__ logit, const int* __restrict__ target,
    const float* __restrict__ image, const float* __restrict__ srcmap,
    const float* __restrict__ dstmap, float* __restrict__ out)
{
    __shared__ float red[NTHR/32];
    const int tid  = threadIdx.x;
    const int lane = tid & 31;
    const int wid  = tid >> 5;

    // ---------------- Phase 1: softmax, CE, staging, compaction -------------
    {
        int t = blockIdx.x * NTHR + tid;            // NBLK*NTHR=75776 >= NPIX
        float ce = 0.f;
        bool active = false;

        if (t < NPIX) {
            int b  = t / HW;
            int hw = t - b * HW;
            int i  = hw / Ww;
            int j  = hw - i * Ww;

            const float* lg = logit + (size_t)b * 3 * HW + hw;
            float l0 = lg[0], l1 = lg[HW], l2 = lg[2*HW];
            float m  = fmaxf(l0, fmaxf(l1, l2));
            float e0 = expf(l0 - m), e1 = expf(l1 - m), e2 = expf(l2 - m);
            float s  = e0 + e1 + e2;
            float inv = 1.f / s;
            float y0 = e0*inv, y1 = e1*inv, y2 = e2*inv;

            int   tg  = target[t];
            float lt  = (tg == 0) ? l0 : ((tg == 1) ? l1 : l2);
            float dst = dstmap[t];
            ce = -((lt - m) - logf(s)) * dst;

            const float* im = image + (size_t)b * 3 * HW + hw;
            float src = srcmap[t];
            int pidx = (b * PH + i + SPAN) * PW + (j + SPAN);
            g_simg[pidx] = make_float4(10.f*SSC*im[0], 10.f*SSC*im[HW],
                                       10.f*SSC*im[2*HW], src);
            g_yhat[pidx] = make_float4(src*y0, src*y1, src*y2, 0.f);
            g_cw[t]      = make_float4(y0, y1, y2, 0.f);

            active = (dst == 0.0f);                 // m_dst = 1 - dst
        }

        // warp-aggregated compaction (NPIX % 32 == 0 -> warps are uniform)
        unsigned mask = __ballot_sync(0xffffffffu, active);
        if (mask) {
            int leader = __ffs(mask) - 1;
            int base   = 0;
            if (lane == leader) base = atomicAdd(&g_count, __popc(mask));
            base = __shfl_sync(0xffffffffu, base, leader);
            if (active) g_list[base + __popc(mask & ((1u << lane) - 1))] = t;
        }

        // block-reduce CE
        #pragma unroll
        for (int s2 = 16; s2 > 0; s2 >>= 1)
            ce += __shfl_xor_sync(0xffffffffu, ce, s2);
        if (lane == 0) red[wid] = ce;
        __syncthreads();
        if (wid == 0) {
            float v = (lane < NTHR/32) ? red[lane] : 0.f;
            #pragma unroll
            for (int s2 = 8; s2 > 0; s2 >>= 1)
                v += __shfl_xor_sync(0xffffffffu, v, s2);
            if (lane == 0) atomicAdd(&g_ce, (double)v);
        }
    }

    // ---------------- Grid barrier ------------------------------------------
    __syncthreads();
    if (tid == 0) {
        __threadfence();
        atomicAdd(&g_bar1, 1u);
        while (*(volatile unsigned*)&g_bar1 < NBLK) { __nanosleep(32); }
        __threadfence();
    }
    __syncthreads();

    // ---------------- Phase 2: window loop (dynamic half-window units) ------
    {
        const int count  = *(volatile int*)&g_count;
        const int nunits = ((count + 31) >> 5) * 2;  // 2 half-windows per chunk
        float acc = 0.f;

        for (;;) {
            int u = 0;
            if (lane == 0) u = (int)atomicAdd(&g_unit, 1u);
            u = __shfl_sync(0xffffffffu, u, 0);
            if (u >= nunits) break;

            int chunk = u >> 1;
            int half  = u & 1;
            int p     = (chunk << 5) + lane;
            if (p < count) {
                int t  = g_list[p];
                int b  = t / HW;
                int hw = t - b * HW;
                int i  = hw / Ww;
                int j  = hw - i * Ww;
                int base = (b * PH + i) * PW + j;    // padded window corner

                float4 ci = g_simg[base + SPAN*PW + SPAN];
                float c0 = 0.1f*ci.x, c1 = 0.1f*ci.y, c2 = 0.1f*ci.z;
                float4 cy = g_cw[t];
                float y0p = cy.x, y1p = cy.y, y2p = cy.z;

                float fj[KK];
                #pragma unroll
                for (int d = 0; d < KK; d++) {
                    float xj = (float)(5*j - d + SPAN) * (1.f/6.f);
                    fj[d] = ex2f(xj*xj*C1);
                }

                int dlo = half ? 12 : 0;
                int dhi = half ? KK : 12;
                #pragma unroll 1
                for (int di = dlo; di < dhi; di++) {
                    float xi = (float)(5*i - di + SPAN) * (1.f/6.f);
                    float fi = ex2f(xi*xi*C1);
                    const float4* pim = g_simg + base + di*PW;
                    const float4* pyh = g_yhat + base + di*PW;
                    #pragma unroll
                    for (int dj = 0; dj < KK; dj++) {
                        float4 nb = __ldg(pim + dj);   // scaled img + src gate
                        float4 ny = __ldg(pyh + dj);   // src-gated softmax
                        float d0 = c0 - nb.x, d1 = c1 - nb.y, d2 = c2 - nb.z;
                        float ssn = d0 * (-d0);
                        ssn = fmaf(d1, -d1, ssn);
                        ssn = fmaf(d2, -d2, ssn);
                        float krgb = ex2f(ssn);              // exp(-0.5*||d||^2)
                        // sum_c src*y_qc*(1-y_pc) = src - (src*y_q).y_p
                        float sn = fmaf(ny.x, -y0p, nb.w);
                        sn = fmaf(ny.y, -y1p, sn);
                        sn = fmaf(ny.z, -y2p, sn);
                        float km = fmaf(fi, fj[dj], krgb);   // k_rgb + k_xy
                        acc = fmaf(km, sn, acc);
                    }
                }
            }
        }

        // block-reduce gcrf partial
        #pragma unroll
        for (int s2 = 16; s2 > 0; s2 >>= 1)
            acc += __shfl_xor_sync(0xffffffffu, acc, s2);
        __syncthreads();                      // red[] reuse after phase 1
        if (lane == 0) red[wid] = acc;
        __syncthreads();
        if (wid == 0) {
            float v = (lane < NTHR/32) ? red[lane] : 0.f;
            #pragma unroll
            for (int s2 = 8; s2 > 0; s2 >>= 1)
                v += __shfl_xor_sync(0xffffffffu, v, s2);
            if (lane == 0) atomicAdd(&g_gcrf, (double)v);
        }
    }

    // ---------------- Fin: last block writes output + resets state ----------
    __syncthreads();
    if (tid == 0) {
        __threadfence();
        unsigned d = atomicAdd(&g_done, 1u);
        if (d == NBLK - 1) {                  // everyone's atomics are visible
            __threadfence();
            out[0] = (float)((g_ce + 0.15 * g_gcrf) / (double)NPIX);
            g_ce = 0.0; g_gcrf = 0.0;
            g_count = 0; g_bar1 = 0; g_unit = 0; g_done = 0;
        }
    }
}

extern "C" void kernel_launch(void* const* d_in, const int* in_sizes, int n_in,
                              void* d_out, int out_size)
{
    const float* logit  = (const float*)d_in[0];
    const int*   target = (const int*)  d_in[1];
    const float* image  = (const float*)d_in[2];
    const float* srcmap = (const float*)d_in[3];
    const float* dstmap = (const float*)d_in[4];
    float* out = (float*)d_out;

    fused_kernel<<<NBLK, NTHR>>>(logit, target, image, srcmap, dstmap, out);
}

// round 7
// speedup vs baseline: 1.7757x; 1.5867x over previous
#include <cuda_runtime.h>
#include <cuda_fp16.h>

// Problem constants
#define Bz   2
#define Hh   160
#define Ww   160
#define SPAN 11
#define KK   23              // 2*SPAN+1
#define PH   (Hh + 2*SPAN)   // 182
#define PW   (Ww + 2*SPAN)   // 182
#define NPIX (Bz*Hh*Ww)      // 51200
#define HW   (Hh*Ww)

#define NBLK 148             // one persistent block per SM
#define NTHR 512

// s = sqrt(0.5*log2(e)); neighbor staged pre-scaled by 10*s, center by s,
// so d = s*(im_c - 10*im_p) and exp arg is simply -sum(d^2)   (ref's sigma bug)
#define SSC  0.8493218f
#define C1   (-0.72134752f)  // -0.5*log2(e), for spatial kernel

// __device__ globals: zero-initialized at load; pad regions never written;
// mutable state self-resets at the end of each launch (graph-replay safe).
__device__ uint4    g_pk[Bz*PH*PW];    // 8 halves: {10s*r,10s*g},{10s*b,src},{sy0,sy1},{sy2,0}
__device__ float4   g_crgb[NPIX];      // center rgb scaled by SSC ONLY (float, exact)
__device__ float4   g_cw[NPIX];        // center softmax {y0,y1,y2,0} (float)
__device__ int      g_list[NPIX];      // compacted active-pixel indices
__device__ int      g_count;
__device__ unsigned g_bar1;            // grid barrier (prep -> window)
__device__ unsigned g_unit;            // dynamic work counter (window phase)
__device__ unsigned g_done;            // completion ticket (fin phase)
__device__ double   g_ce;
__device__ double   g_gcrf;

__device__ __forceinline__ float ex2f(float x) {
    float y;
    asm("ex2.approx.f32 %0, %1;" : "=f"(y) : "f"(x));
    return y;
}

__device__ __forceinline__ unsigned h2u(__half2 h) {
    return *reinterpret_cast<unsigned*>(&h);
}

__global__ void __launch_bounds__(NTHR, 1) fused_kernel(
    const float* __restrict__ logit, const int* __restrict__ target,
    const float* __restrict__ image, const float* __restrict__ srcmap,
    const float* __restrict__ dstmap, float* __restrict__ out)
{
    __shared__ float red[NTHR/32];
    const int tid  = threadIdx.x;
    const int lane = tid & 31;
    const int wid  = tid >> 5;

    // ---------------- Phase 1: softmax, CE, staging, compaction -------------
    {
        int t = blockIdx.x * NTHR + tid;            // NBLK*NTHR=75776 >= NPIX
        float ce = 0.f;
        bool active = false;

        if (t < NPIX) {
            int b  = t / HW;
            int hw = t - b * HW;
            int i  = hw / Ww;
            int j  = hw - i * Ww;

            const float* lg = logit + (size_t)b * 3 * HW + hw;
            float l0 = lg[0], l1 = lg[HW], l2 = lg[2*HW];
            float m  = fmaxf(l0, fmaxf(l1, l2));
            float e0 = expf(l0 - m), e1 = expf(l1 - m), e2 = expf(l2 - m);
            float s  = e0 + e1 + e2;
            float inv = 1.f / s;
            float y0 = e0*inv, y1 = e1*inv, y2 = e2*inv;

            int   tg  = target[t];
            float lt  = (tg == 0) ? l0 : ((tg == 1) ? l1 : l2);
            float dst = dstmap[t];
            ce = -((lt - m) - logf(s)) * dst;

            const float* im = image + (size_t)b * 3 * HW + hw;
            float src = srcmap[t];
            // neighbor copy: scaled by 10*SSC (the /SIG_RGB=×10 from the ref bug)
            float sr = 10.f*SSC*im[0], sg = 10.f*SSC*im[HW], sb = 10.f*SSC*im[2*HW];

            int pidx = (b * PH + i + SPAN) * PW + (j + SPAN);
            uint4 pk;
            pk.x = h2u(__floats2half2_rn(sr, sg));
            pk.y = h2u(__floats2half2_rn(sb, src));
            pk.z = h2u(__floats2half2_rn(src*y0, src*y1));
            pk.w = h2u(__floats2half2_rn(src*y2, 0.f));
            g_pk[pidx]  = pk;
            // center copy: scaled by SSC ONLY (no ×10)
            g_crgb[t]   = make_float4(SSC*im[0], SSC*im[HW], SSC*im[2*HW], 0.f);
            g_cw[t]     = make_float4(y0, y1, y2, 0.f);

            active = (dst == 0.0f);                 // m_dst = 1 - dst
        }

        // warp-aggregated compaction (NPIX % 32 == 0 -> warps are uniform)
        unsigned mask = __ballot_sync(0xffffffffu, active);
        if (mask) {
            int leader = __ffs(mask) - 1;
            int base   = 0;
            if (lane == leader) base = atomicAdd(&g_count, __popc(mask));
            base = __shfl_sync(0xffffffffu, base, leader);
            if (active) g_list[base + __popc(mask & ((1u << lane) - 1))] = t;
        }

        // block-reduce CE
        #pragma unroll
        for (int s2 = 16; s2 > 0; s2 >>= 1)
            ce += __shfl_xor_sync(0xffffffffu, ce, s2);
        if (lane == 0) red[wid] = ce;
        __syncthreads();
        if (wid == 0) {
            float v = (lane < NTHR/32) ? red[lane] : 0.f;
            #pragma unroll
            for (int s2 = 8; s2 > 0; s2 >>= 1)
                v += __shfl_xor_sync(0xffffffffu, v, s2);
            if (lane == 0) atomicAdd(&g_ce, (double)v);
        }
    }

    // ---------------- Grid barrier ------------------------------------------
    __syncthreads();
    if (tid == 0) {
        __threadfence();
        atomicAdd(&g_bar1, 1u);
        while (*(volatile unsigned*)&g_bar1 < NBLK) { __nanosleep(32); }
        __threadfence();
    }
    __syncthreads();

    // ---------------- Phase 2: window loop (dynamic half-window units) ------
    {
        const int count  = *(volatile int*)&g_count;
        const int nunits = ((count + 31) >> 5) * 2;  // 2 half-windows per chunk
        float acc = 0.f;

        for (;;) {
            int u = 0;
            if (lane == 0) u = (int)atomicAdd(&g_unit, 1u);
            u = __shfl_sync(0xffffffffu, u, 0);
            if (u >= nunits) break;

            int chunk = u >> 1;
            int half  = u & 1;
            int p     = (chunk << 5) + lane;
            if (p < count) {
                int t  = g_list[p];
                int b  = t / HW;
                int hw = t - b * HW;
                int i  = hw / Ww;
                int j  = hw - i * Ww;
                int base = (b * PH + i) * PW + j;    // padded window corner

                float4 cr = g_crgb[t];
                float c0 = cr.x, c1 = cr.y, c2 = cr.z;   // SSC-scaled center rgb
                float4 cy = g_cw[t];
                float y0p = cy.x, y1p = cy.y, y2p = cy.z;

                float fj[KK];
                #pragma unroll
                for (int d = 0; d < KK; d++) {
                    float xj = (float)(5*j - d + SPAN) * (1.f/6.f);
                    fj[d] = ex2f(xj*xj*C1);
                }

                int dlo = half ? 12 : 0;
                int dhi = half ? KK : 12;
                #pragma unroll 1
                for (int di = dlo; di < dhi; di++) {
                    float xi = (float)(5*i - di + SPAN) * (1.f/6.f);
                    float fi = ex2f(xi*xi*C1);
                    const uint4* ppk = g_pk + base + di*PW;
                    #pragma unroll
                    for (int dj = 0; dj < KK; dj++) {
                        uint4 v = __ldg(ppk + dj);
                        float2 rg  = __half22float2(*reinterpret_cast<const __half2*>(&v.x));
                        float2 bs  = __half22float2(*reinterpret_cast<const __half2*>(&v.y));
                        float2 y01 = __half22float2(*reinterpret_cast<const __half2*>(&v.z));
                        float2 y2_ = __half22float2(*reinterpret_cast<const __half2*>(&v.w));
                        float d0 = c0 - rg.x, d1 = c1 - rg.y, d2 = c2 - bs.x;
                        float ssn = d0 * (-d0);
                        ssn = fmaf(d1, -d1, ssn);
                        ssn = fmaf(d2, -d2, ssn);
                        float krgb = ex2f(ssn);              // exp(-0.5*||d||^2)
                        // sum_c src*y_qc*(1-y_pc) = src - (src*y_q).y_p
                        float sn = fmaf(y01.x, -y0p, bs.y);
                        sn = fmaf(y01.y, -y1p, sn);
                        sn = fmaf(y2_.x, -y2p, sn);
                        float km = fmaf(fi, fj[dj], krgb);   // k_rgb + k_xy
                        acc = fmaf(km, sn, acc);
                    }
                }
            }
        }

        // block-reduce gcrf partial
        #pragma unroll
        for (int s2 = 16; s2 > 0; s2 >>= 1)
            acc += __shfl_xor_sync(0xffffffffu, acc, s2);
        __syncthreads();                      // red[] reuse after phase 1
        if (lane == 0) red[wid] = acc;
        __syncthreads();
        if (wid == 0) {
            float v = (lane < NTHR/32) ? red[lane] : 0.f;
            #pragma unroll
            for (int s2 = 8; s2 > 0; s2 >>= 1)
                v += __shfl_xor_sync(0xffffffffu, v, s2);
            if (lane == 0) atomicAdd(&g_gcrf, (double)v);
        }
    }

    // ---------------- Fin: last block writes output + resets state ----------
    __syncthreads();
    if (tid == 0) {
        __threadfence();
        unsigned d = atomicAdd(&g_done, 1u);
        if (d == NBLK - 1) {                  // everyone's atomics are visible
            __threadfence();
            out[0] = (float)((g_ce + 0.15 * g_gcrf) / (double)NPIX);
            g_ce = 0.0; g_gcrf = 0.0;
            g_count = 0; g_bar1 = 0; g_unit = 0; g_done = 0;
        }
    }
}

extern "C" void kernel_launch(void* const* d_in, const int* in_sizes, int n_in,
                              void* d_out, int out_size)
{
    const float* logit  = (const float*)d_in[0];
    const int*   target = (const int*)  d_in[1];
    const float* image  = (const float*)d_in[2];
    const float* srcmap = (const float*)d_in[3];
    const float* dstmap = (const float*)d_in[4];
    float* out = (float*)d_out;

    fused_kernel<<<NBLK, NTHR>>>(logit, target, image, srcmap, dstmap, out);
}